// round 6
// baseline (speedup 1.0000x reference)
#include <cuda_runtime.h>
#include <cuda_bf16.h>

// TransferMatrixMethod: B=256, L=64 (62 interior), W=512.
// Layer matrices [[a, ib],[ic, d]] (real a,b,c,d) closed under multiplication.
// Track A,B,C,Dt(=-D); f32x2 lanes = 2 adjacent wavelengths per thread.
//
// 4-way layer split (R5 algebra, verified): layers padded to 64 with identity
// (nd=0 -> sin=0,cos=1 -> exact no-op). lane = h*8+c; h owns layers [16h,16h+16).
// Combine via shuffle rounds (lane xor 8, lane xor 16):
//   Z = L*R:  Z_A = LA*RA - LB*RC       Z_B  = LA*RB - LB*RDt
//             Z_C = LC*RA - LDt*RC      Z_Dt = -LDt*RDt + LC*RB
//
// 8192 warps total (2048 blocks x 128 thr) to cover MUFU latency; MUFU pipe
// (sincos) is the predicted floor at ~3.6us.
//
// Epilogue: E=(A+1e-9)+i*B*nsub, H=D*nsub+i*C,
//   r=(nin*E-H)/(nin*E+H), R=|num|^2/|den|^2 -> one division per point.

#define LTOT 64
#define WDIM 512
#define TPB  128

typedef unsigned long long u64;

__device__ __forceinline__ u64 pack2(float lo, float hi) {
    u64 r;
    asm("mov.b64 %0, {%1, %2};" : "=l"(r) : "f"(lo), "f"(hi));
    return r;
}
__device__ __forceinline__ void unpack2(float& lo, float& hi, u64 v) {
    asm("mov.b64 {%0, %1}, %2;" : "=f"(lo), "=f"(hi) : "l"(v));
}
__device__ __forceinline__ u64 mul2(u64 a, u64 b) {
    u64 r;
    asm("mul.rn.f32x2 %0, %1, %2;" : "=l"(r) : "l"(a), "l"(b));
    return r;
}
__device__ __forceinline__ u64 fma2(u64 a, u64 b, u64 c) {
    u64 r;
    asm("fma.rn.f32x2 %0, %1, %2, %3;" : "=l"(r) : "l"(a), "l"(b), "l"(c));
    return r;
}
__device__ __forceinline__ u64 neg2(u64 a) {
    return a ^ 0x8000000080000000ULL;
}

__device__ __forceinline__ void combine(u64& A, u64& B, u64& C, u64& Dt,
                                        int xm, bool upper)
{
    const unsigned FULL = 0xffffffffu;
    u64 pA  = __shfl_xor_sync(FULL, A,  xm);
    u64 pB  = __shfl_xor_sync(FULL, B,  xm);
    u64 pC  = __shfl_xor_sync(FULL, C,  xm);
    u64 pDt = __shfl_xor_sync(FULL, Dt, xm);

    u64 LA  = upper ? pA  : A;   u64 RA  = upper ? A  : pA;
    u64 LB  = upper ? pB  : B;   u64 RB  = upper ? B  : pB;
    u64 LC  = upper ? pC  : C;   u64 RC  = upper ? C  : pC;
    u64 LDt = upper ? pDt : Dt;  u64 RDt = upper ? Dt : pDt;

    u64 nLB  = neg2(LB);
    u64 nLDt = neg2(LDt);

    u64 zA  = fma2(nLB,  RC,  mul2(LA, RA));
    u64 zB  = fma2(nLB,  RDt, mul2(LA, RB));
    u64 zC  = fma2(nLDt, RC,  mul2(LC, RA));
    u64 zDt = fma2(nLDt, RDt, mul2(LC, RB));
    A = zA; B = zB; C = zC; Dt = zDt;
}

__global__ __launch_bounds__(TPB)
void tmm_kernel(const float* __restrict__ n_layers,
                const float* __restrict__ d_layers,
                const float* __restrict__ wavelengths,
                float* __restrict__ out)
{
    const int b    = blockIdx.x >> 3;        // 0..255
    const int oct  = blockIdx.x & 7;         // eighth of wavelength axis
    const int t    = threadIdx.x;            // 0..127
    const int lane = t & 31;
    const int wrp  = t >> 5;
    const int h    = lane >> 3;              // layer-split index, 0..3
    const int c    = lane & 7;
    const int chain = wrp * 8 + c;           // 0..31 in block
    const int w0   = oct * 64 + chain * 2;   // first of 2 wavelengths

    // padded layer tables: idx = 17*h + j, j in [0,16); layers 62,63 = identity
    __shared__ float s_nd[68];
    __shared__ u64   s_n2[68];
    __shared__ u64   s_mr2[68];
    __shared__ float s_nin, s_nsub;

    if (t < 64) {
        const int hh = t >> 4, j = t & 15, idx = hh * 17 + j;
        float nv = 1.0f, ndv = 0.0f, mr = -1.0f;
        if (t < 62) {
            nv = n_layers[b * LTOT + t + 1];
            float dv = d_layers[b * LTOT + t + 1];
            ndv = nv * dv;
            mr = -1.0f / (nv + 1e-8f);
        }
        s_nd[idx]  = ndv;
        s_n2[idx]  = pack2(nv, nv);
        s_mr2[idx] = pack2(mr, mr);
    }
    if (t == 64) s_nin  = n_layers[b * LTOT];
    if (t == 65) s_nsub = n_layers[b * LTOT + LTOT - 1];
    __syncthreads();

    const float TWO_PI = 6.28318530717958647692f;
    const float2 lam = *reinterpret_cast<const float2*>(wavelengths + w0);
    const float k0 = __fdividef(TWO_PI, lam.x);
    const float k1 = __fdividef(TWO_PI, lam.y);

    u64 A  = pack2(1.0f, 1.0f);
    u64 Bv = 0ULL;
    u64 C  = 0ULL;
    u64 Dt = pack2(-1.0f, -1.0f);   // -D

    const int base = h * 17;
    #pragma unroll
    for (int j = 0; j < 16; ++j) {
        const float nd  = s_nd[base + j];
        const u64   n2  = s_n2[base + j];
        const u64   mr2 = s_mr2[base + j];

        // |phi| <= ~12: inside MUFU.SIN/COS accurate range (verified R2-R5)
        const float p0 = nd * k0;
        const float p1 = nd * k1;
        float s0, c0, s1, c1;
        __sincosf(p0, &s0, &c0);
        __sincosf(p1, &s1, &c1);

        const u64 sp2 = pack2(s0, s1);
        const u64 cp2 = pack2(c0, c1);

        const u64 ns2  = mul2(sp2, n2);    // { n*sin }
        const u64 msr2 = mul2(sp2, mr2);   // { -sin/(n+eps) }

        u64 nA = fma2(ns2,  Bv, mul2(cp2, A));
        u64 nB = fma2(msr2, A,  mul2(cp2, Bv));
        u64 nC = fma2(ns2,  Dt, mul2(cp2, C));
        u64 nD = fma2(msr2, C,  mul2(cp2, Dt));
        A = nA; Bv = nB; C = nC; Dt = nD;
    }

    // combine 4 splits: round 0 pairs h^1 (lane^8), round 1 pairs h^2 (lane^16)
    combine(A, Bv, C, Dt, 8,  (h & 1) != 0);
    combine(A, Bv, C, Dt, 16, (h & 2) != 0);

    if (h == 0) {
        float A0, A1, B0, B1, C0, C1, Dt0, Dt1;
        unpack2(A0, A1, A);
        unpack2(B0, B1, Bv);
        unpack2(C0, C1, C);
        unpack2(Dt0, Dt1, Dt);

        const float nin  = s_nin;
        const float nsub = s_nsub;

        float R[2];
        #pragma unroll
        for (int i = 0; i < 2; ++i) {
            const float a  = i ? A1 : A0;
            const float bb = i ? B1 : B0;
            const float c2 = i ? C1 : C0;
            const float d  = -(i ? Dt1 : Dt0);

            const float Er = a + 1e-9f;
            const float Ei = bb * nsub;
            const float Hr = d * nsub;
            const float Hi = c2;

            const float numr = fmaf(nin, Er, -Hr);
            const float numi = fmaf(nin, Ei, -Hi);
            const float denr = fmaf(nin, Er,  Hr);
            const float deni = fmaf(nin, Ei,  Hi);

            const float num2 = fmaf(numr, numr, numi * numi);
            const float den2 = fmaf(denr, denr, deni * deni);
            R[i] = num2 / den2;
        }

        *reinterpret_cast<float2*>(out + b * WDIM + w0) = make_float2(R[0], R[1]);
    }
}

extern "C" void kernel_launch(void* const* d_in, const int* in_sizes, int n_in,
                              void* d_out, int out_size)
{
    const float* n_layers    = (const float*)d_in[0];  // (256, 64)
    const float* d_layers    = (const float*)d_in[1];  // (256, 64)
    const float* wavelengths = (const float*)d_in[2];  // (512,)
    float* out = (float*)d_out;                        // (256, 512)

    tmm_kernel<<<2048, TPB>>>(n_layers, d_layers, wavelengths, out);
}